// round 7
// baseline (speedup 1.0000x reference)
#include <cuda_runtime.h>
#include <cstdint>

#define BB 32
#define LL 128
#define FF 128
#define RR 4096
#define HH (RR >> 1)
#define NN 262144
#define NGROUPS (BB * RR)      // 131072
#define CAP 32

// Scratch (allocation-free: __device__ globals).
__device__ int    g_cnt[NGROUPS];
__device__ int    g_slots[NGROUPS * CAP];
__device__ float4 g_cw[NN];    // fused coeffs (d0w0, d1w1, d2w2, d2w3)

__device__ __forceinline__ void acc_fma(float4& a, float c, const float4& v) {
    a.x = fmaf(c, v.x, a.x); a.y = fmaf(c, v.y, a.y);
    a.z = fmaf(c, v.z, a.z); a.w = fmaf(c, v.w, a.w);
}

// coefficient select by merged position p: [0,cc) cons, [cc,cc+ca) car, rest cdr
__device__ __forceinline__ float csel(const float4& c, int p, int cc, int cca, bool odd) {
    return (p < cc) ? (odd ? c.w : c.z) : ((p < cca) ? c.x : c.y);
}

// ---------------------------------------------------------------------------
// Kernel 1: one thread per element — fused coefficients + inverted index.
__global__ void dti_build_kernel(const float4* __restrict__ arg_w,
                                 const float*  __restrict__ op_dist,
                                 const int* __restrict__ batch_idx,
                                 const int* __restrict__ slot_idx,
                                 const int* __restrict__ role_idx,
                                 int n) {
    int e = blockIdx.x * blockDim.x + threadIdx.x;
    if (e >= n) return;
    int b = __ldg(batch_idx + e);
    int s = __ldg(slot_idx + e);
    int j = __ldg(role_idx + e);
    float4 w = __ldg(arg_w + b * LL + s);
    float d0 = __ldg(op_dist + b * 3 + 0);
    float d1 = __ldg(op_dist + b * 3 + 1);
    float d2 = __ldg(op_dist + b * 3 + 2);
    g_cw[e] = make_float4(d0 * w.x, d1 * w.y, d2 * w.z, d2 * w.w);
    int key = (b << 12) + j;
    int pos = atomicAdd(&g_cnt[key], 1);
    if (pos < CAP) g_slots[key * CAP + pos] = e;
}

// ---------------------------------------------------------------------------
// Kernel 2: all output rows, no atomics, no init pass.
//   warps [0, 65536):      one warp per LOW row (rr < H): cons+car+cdr merged
//                          into a single strip-4 loop (one latency level).
//   warps [65536, 98304):  one warp per HIGH row pair: cons only.
__global__ __launch_bounds__(256)
void dti_out_kernel(const float4* __restrict__ mem,
                    const float4* __restrict__ root_filler,
                    const float*  __restrict__ op_dist,
                    float4* __restrict__ out) {
    int wid = (blockIdx.x * blockDim.x + threadIdx.x) >> 5;
    int lane = threadIdx.x & 31;

    if (wid < BB * HH) {
        // ---------------- low row: rr in [0, H) ----------------
        int b = wid >> 11;
        int rr = wid & (HH - 1);
        int gbase = b << 12;

        // independent up-front index loads (one latency level)
        int gc = gbase + (rr >> 1);
        int cntc = min(__ldg(&g_cnt[gc]), CAP);
        int svc = __ldg(&g_slots[gc * CAP + lane]);
        int2 c2 = __ldg((const int2*)&g_cnt[gbase + 2 * rr]);
        int sb = (gbase + 2 * rr) * CAP;
        int sva = __ldg(&g_slots[sb + lane]);
        int svb = __ldg(&g_slots[sb + CAP + lane]);
        int cnta = min(c2.x, CAP);
        int cntb = (rr == 0) ? 0 : min(c2.y, CAP);

        int cc = cntc, cca = cntc + cnta;
        int T = cca + cntb;
        bool odd = (rr & 1);

        // warp-cooperative merge: lane p holds p-th id of (cons||car||cdr)
        int vc = __shfl_sync(0xffffffffu, svc, lane & 31);
        int va = __shfl_sync(0xffffffffu, sva, (lane - cc) & 31);
        int vb = __shfl_sync(0xffffffffu, svb, (lane - cca) & 31);
        int m = (lane < cc) ? vc : ((lane < cca) ? va : vb);

        float4 a = make_float4(0.f, 0.f, 0.f, 0.f);

        int Tm = min(T, 32);
        #pragma unroll 1
        for (int p = 0; p < Tm; p += 4) {
            int e0 = __shfl_sync(0xffffffffu, m, p);
            int e1 = __shfl_sync(0xffffffffu, m, (p + 1) & 31);
            int e2 = __shfl_sync(0xffffffffu, m, (p + 2) & 31);
            int e3 = __shfl_sync(0xffffffffu, m, (p + 3) & 31);
            bool h1 = p + 1 < Tm, h2 = p + 2 < Tm, h3 = p + 3 < Tm;
            float4 c0, v0, c1, v1, c2_, v2, c3, v3;
            c0 = __ldg(&g_cw[e0]); v0 = __ldg(mem + (size_t)e0 * (FF/4) + lane);
            if (h1) { c1  = __ldg(&g_cw[e1]); v1 = __ldg(mem + (size_t)e1 * (FF/4) + lane); }
            if (h2) { c2_ = __ldg(&g_cw[e2]); v2 = __ldg(mem + (size_t)e2 * (FF/4) + lane); }
            if (h3) { c3  = __ldg(&g_cw[e3]); v3 = __ldg(mem + (size_t)e3 * (FF/4) + lane); }
            acc_fma(a, csel(c0, p, cc, cca, odd), v0);
            if (h1) acc_fma(a, csel(c1,  p + 1, cc, cca, odd), v1);
            if (h2) acc_fma(a, csel(c2_, p + 2, cc, cca, odd), v2);
            if (h3) acc_fma(a, csel(c3,  p + 3, cc, cca, odd), v3);
        }
        // fallback tail for T>32 (probability ~0; correctness guard)
        #pragma unroll 1
        for (int p = 32; p < T; p++) {
            int e;
            if (p < cc)       e = __ldg(&g_slots[gc * CAP + p]);
            else if (p < cca) e = __ldg(&g_slots[sb + (p - cc)]);
            else              e = __ldg(&g_slots[sb + CAP + (p - cca)]);
            float4 c = __ldg(&g_cw[e]);
            float4 v = __ldg(mem + (size_t)e * (FF/4) + lane);
            acc_fma(a, csel(c, p, cc, cca, odd), v);
        }

        if (rr == 1) {
            float d2 = __ldg(op_dist + b * 3 + 2);
            float4 rf = __ldg(root_filler + b * (FF / 4) + lane);
            acc_fma(a, d2, rf);
        }
        __stcs(out + ((size_t)(gbase + rr)) * (FF / 4) + lane, a);
    } else {
        // ---------------- high pair: rows 2k, 2k+1, k in [H/2, H) ----------------
        int t = wid - BB * HH;
        int b = t >> 10;
        int k = (HH / 2) + (t & 1023);
        int g = (b << 12) + k;
        int cnt = min(__ldg(&g_cnt[g]), CAP);
        int sv = __ldg(&g_slots[g * CAP + lane]);

        float4 a0 = make_float4(0.f, 0.f, 0.f, 0.f);
        float4 a1 = make_float4(0.f, 0.f, 0.f, 0.f);
        #pragma unroll 1
        for (int i = 0; i < cnt; i += 4) {
            int e0 = __shfl_sync(0xffffffffu, sv, i);
            int e1 = __shfl_sync(0xffffffffu, sv, (i + 1) & 31);
            int e2 = __shfl_sync(0xffffffffu, sv, (i + 2) & 31);
            int e3 = __shfl_sync(0xffffffffu, sv, (i + 3) & 31);
            bool h1 = i + 1 < cnt, h2 = i + 2 < cnt, h3 = i + 3 < cnt;
            float4 c0, v0, c1, v1, c2_, v2, c3, v3;
            c0 = __ldg(&g_cw[e0]); v0 = __ldg(mem + (size_t)e0 * (FF/4) + lane);
            if (h1) { c1  = __ldg(&g_cw[e1]); v1 = __ldg(mem + (size_t)e1 * (FF/4) + lane); }
            if (h2) { c2_ = __ldg(&g_cw[e2]); v2 = __ldg(mem + (size_t)e2 * (FF/4) + lane); }
            if (h3) { c3  = __ldg(&g_cw[e3]); v3 = __ldg(mem + (size_t)e3 * (FF/4) + lane); }
            acc_fma(a0, c0.z, v0); acc_fma(a1, c0.w, v0);
            if (h1) { acc_fma(a0, c1.z,  v1); acc_fma(a1, c1.w,  v1); }
            if (h2) { acc_fma(a0, c2_.z, v2); acc_fma(a1, c2_.w, v2); }
            if (h3) { acc_fma(a0, c3.z,  v3); acc_fma(a1, c3.w,  v3); }
        }
        size_t o = ((size_t)((b << 12) + 2 * k)) * (FF / 4) + lane;
        __stcs(out + o, a0);
        __stcs(out + o + (FF / 4), a1);
    }
}

// ---------------------------------------------------------------------------
extern "C" void kernel_launch(void* const* d_in, const int* in_sizes, int n_in,
                              void* d_out, int out_size) {
    const float* mem = (const float*)d_in[0];
    const float* aw  = (const float*)d_in[1];
    const float* rf  = (const float*)d_in[2];
    const float* od  = (const float*)d_in[3];
    const int* bi    = (const int*)d_in[4];
    const int* si    = (const int*)d_in[5];
    const int* ri    = (const int*)d_in[6];
    float4* out      = (float4*)d_out;

    int n = in_sizes[4];

    void* cnt_ptr = nullptr;
    cudaGetSymbolAddress(&cnt_ptr, g_cnt);
    cudaMemsetAsync(cnt_ptr, 0, NGROUPS * sizeof(int), 0);

    dti_build_kernel<<<(n + 255) / 256, 256>>>((const float4*)aw, od, bi, si, ri, n);

    int total_warps = BB * HH + BB * (HH / 2);   // 98304
    dti_out_kernel<<<total_warps * 32 / 256, 256>>>(
        (const float4*)mem, (const float4*)rf, od, out);
}